// round 13
// baseline (speedup 1.0000x reference)
#include <cuda_runtime.h>
#include <cstdint>

#define NM 64
#define MAXN 262144

// ---------------- scratch ---------------------------------------------------
__device__ int g_counts[NM];        // statically zero-init; re-zeroed by scan_kernel
__device__ int g_offsets[NM + 1];
__device__ int g_cursor[NM];
__device__ int g_perm[MAXN];

// ---------------- prep kernels ----------------------------------------------
__global__ void hist_kernel(const int* __restrict__ idx, int N) {
    __shared__ int lc[NM];
    if (threadIdx.x < NM) lc[threadIdx.x] = 0;
    __syncthreads();
    for (int i = blockIdx.x * blockDim.x + threadIdx.x; i < N; i += gridDim.x * blockDim.x)
        atomicAdd(&lc[idx[i]], 1);
    __syncthreads();
    if (threadIdx.x < NM) atomicAdd(&g_counts[threadIdx.x], lc[threadIdx.x]);
}

__global__ void scan_kernel() {
    __shared__ int s[NM];
    int t = threadIdx.x;
    s[t] = g_counts[t];
    __syncthreads();
    if (t == 0) {
        int acc = 0;
        for (int i = 0; i < NM; i++) { int c = s[i]; s[i] = acc; acc += c; }
        g_offsets[NM] = acc;
    }
    __syncthreads();
    g_offsets[t] = s[t];
    g_cursor[t]  = s[t];
    g_counts[t]  = 0;     // pre-zero for the next kernel_launch invocation
}

__global__ void scatter_kernel(const int* __restrict__ idx, int N) {
    __shared__ int lc[NM];
    __shared__ int lbase[NM];
    int t = threadIdx.x;
    int per = (N + gridDim.x - 1) / gridDim.x;
    int lo = blockIdx.x * per;
    int hi = min(lo + per, N);
    if (t < NM) lc[t] = 0;
    __syncthreads();
    for (int i = lo + t; i < hi; i += blockDim.x)
        atomicAdd(&lc[idx[i]], 1);
    __syncthreads();
    if (t < NM) { lbase[t] = atomicAdd(&g_cursor[t], lc[t]); lc[t] = 0; }
    __syncthreads();
    for (int i = lo + t; i < hi; i += blockDim.x) {
        int m = idx[i];
        int r = atomicAdd(&lc[m], 1);
        g_perm[lbase[m] + r] = i;
    }
}

// ---------------- mma helpers ------------------------------------------------
__device__ __forceinline__ uint32_t packh2(float lo, float hi) {
    uint32_t u;
    asm("cvt.rn.f16x2.f32 %0, %1, %2;" : "=r"(u) : "f"(hi), "f"(lo));
    return u;
}

// relu on a packed f16x2 (sign-exact vs f32 fmax-then-pack)
__device__ __forceinline__ uint32_t hmax2z(uint32_t p) {
    uint32_t r;
    asm("max.f16x2 %0, %1, %2;" : "=r"(r) : "r"(p), "r"(0u));
    return r;
}

__device__ __forceinline__ void mma_f16_k8(float* d, uint32_t a0, uint32_t a1, uint32_t b0) {
    asm volatile(
        "mma.sync.aligned.m16n8k8.row.col.f32.f16.f16.f32 "
        "{%0,%1,%2,%3}, {%4,%5}, {%6}, {%0,%1,%2,%3};"
        : "+f"(d[0]), "+f"(d[1]), "+f"(d[2]), "+f"(d[3])
        : "r"(a0), "r"(a1), "r"(b0));
}

__device__ __forceinline__ void mma_f16_k16(float* d, uint32_t a0, uint32_t a1,
                                            uint32_t a2, uint32_t a3,
                                            uint32_t b0, uint32_t b1) {
    asm volatile(
        "mma.sync.aligned.m16n8k16.row.col.f32.f16.f16.f32 "
        "{%0,%1,%2,%3}, {%4,%5,%6,%7}, {%8,%9}, {%0,%1,%2,%3};"
        : "+f"(d[0]), "+f"(d[1]), "+f"(d[2]), "+f"(d[3])
        : "r"(a0), "r"(a1), "r"(a2), "r"(a3), "r"(b0), "r"(b1));
}

// ---------------- SMEM layout (floats) ---------------------------------------
// BF per layer = 4kk * 4pair * 32 lanes * uint4 = 512 uint4 = 2048 floats.
#define OFF_STAGE 0        // 128 rows x 4 uints (x as f16x2, K padded to 8)
#define OFF_B0F   512      // layer0 B frags: 8nn x 32 lanes x uint = 256
#define OFF_BF    768      // layers 1..3 B frags: 3 x 2048 fl = 6144
#define OFF_GHC   6912     // interleaved G|H float4 table: 4 layers x 128 = 512
#define OFF_BIAS  7424     // layers 1..3 bias: 3 x 64 = 192
#define OFF_HF    7616     // head frags: 4kk x 32 lanes x uint2 = 256
#define OFF_B4    7872     // 4
#define SMEM_FLOATS 7876

// Fused LayerNorm + ReLU on TWO warp m-tiles held as D fragments (bias already
// accumulated inside the mma). ghc points at this layer's interleaved G|H
// table: float4 {Gx, Gy, Hx, Hy} at [nn*16 + 4q].
__device__ __forceinline__ void ln16x2_pack(float v[8][4], float u[8][4],
                                            const float* ghc, int q,
                                            uint32_t* ap0, uint32_t* ap1,
                                            uint32_t* bp0, uint32_t* bp1) {
    float vs0 = 0.f, vs1 = 0.f, vq0 = 0.f, vq1 = 0.f;
    float us0 = 0.f, us1 = 0.f, uq0 = 0.f, uq1 = 0.f;
#pragma unroll
    for (int nn = 0; nn < 8; nn++) {
        vs0 += v[nn][0]; vq0 = fmaf(v[nn][0], v[nn][0], vq0);
        vs0 += v[nn][1]; vq0 = fmaf(v[nn][1], v[nn][1], vq0);
        vs1 += v[nn][2]; vq1 = fmaf(v[nn][2], v[nn][2], vq1);
        vs1 += v[nn][3]; vq1 = fmaf(v[nn][3], v[nn][3], vq1);
        us0 += u[nn][0]; uq0 = fmaf(u[nn][0], u[nn][0], uq0);
        us0 += u[nn][1]; uq0 = fmaf(u[nn][1], u[nn][1], uq0);
        us1 += u[nn][2]; uq1 = fmaf(u[nn][2], u[nn][2], uq1);
        us1 += u[nn][3]; uq1 = fmaf(u[nn][3], u[nn][3], uq1);
    }
#pragma unroll
    for (int msk = 1; msk <= 2; msk <<= 1) {
        vs0 += __shfl_xor_sync(0xffffffffu, vs0, msk);
        vq0 += __shfl_xor_sync(0xffffffffu, vq0, msk);
        vs1 += __shfl_xor_sync(0xffffffffu, vs1, msk);
        vq1 += __shfl_xor_sync(0xffffffffu, vq1, msk);
        us0 += __shfl_xor_sync(0xffffffffu, us0, msk);
        uq0 += __shfl_xor_sync(0xffffffffu, uq0, msk);
        us1 += __shfl_xor_sync(0xffffffffu, us1, msk);
        uq1 += __shfl_xor_sync(0xffffffffu, uq1, msk);
    }
    float vmu0 = vs0 * 0.015625f, vmu1 = vs1 * 0.015625f;
    float umu0 = us0 * 0.015625f, umu1 = us1 * 0.015625f;
    float vrs0 = rsqrtf(fmaf(-vmu0, vmu0, vq0 * 0.015625f) + 1e-5f);
    float vrs1 = rsqrtf(fmaf(-vmu1, vmu1, vq1 * 0.015625f) + 1e-5f);
    float urs0 = rsqrtf(fmaf(-umu0, umu0, uq0 * 0.015625f) + 1e-5f);
    float urs1 = rsqrtf(fmaf(-umu1, umu1, uq1 * 0.015625f) + 1e-5f);
    float vc0 = -vmu0 * vrs0, vc1 = -vmu1 * vrs1;
    float uc0 = -umu0 * urs0, uc1 = -umu1 * urs1;
    const float4* gh4 = (const float4*)(ghc + 4 * q);
#pragma unroll
    for (int nn = 0; nn < 8; nn++) {
        float4 gh = gh4[nn * 4];   // {Gx, Gy, Hx, Hy}
        float t0 = fmaf(fmaf(v[nn][0], vrs0, vc0), gh.x, gh.z);
        float t1 = fmaf(fmaf(v[nn][1], vrs0, vc0), gh.y, gh.w);
        float t2 = fmaf(fmaf(v[nn][2], vrs1, vc1), gh.x, gh.z);
        float t3 = fmaf(fmaf(v[nn][3], vrs1, vc1), gh.y, gh.w);
        ap0[nn] = hmax2z(packh2(t0, t1));
        ap1[nn] = hmax2z(packh2(t2, t3));
        float s0 = fmaf(fmaf(u[nn][0], urs0, uc0), gh.x, gh.z);
        float s1 = fmaf(fmaf(u[nn][1], urs0, uc0), gh.y, gh.w);
        float s2 = fmaf(fmaf(u[nn][2], urs1, uc1), gh.x, gh.z);
        float s3 = fmaf(fmaf(u[nn][3], urs1, uc1), gh.y, gh.w);
        bp0[nn] = hmax2z(packh2(s0, s1));
        bp1[nn] = hmax2z(packh2(s2, s3));
    }
}

// 592 blocks = one exact wave at 4 blocks/SM on 148 SMs.
// block b: model m = b % 64, chunk j = b / 64. Models 0..15 have 10 blocks, 16..63 have 9.
__global__ void __launch_bounds__(128, 4) mlp_kernel(
    const float* __restrict__ x,
    const float* __restrict__ W0, const float* __restrict__ B0,
    const float* __restrict__ G0, const float* __restrict__ H0,
    const float* __restrict__ W1, const float* __restrict__ B1,
    const float* __restrict__ G1, const float* __restrict__ H1,
    const float* __restrict__ W2, const float* __restrict__ B2,
    const float* __restrict__ G2, const float* __restrict__ H2,
    const float* __restrict__ W3, const float* __restrict__ B3,
    const float* __restrict__ G3, const float* __restrict__ H3,
    const float* __restrict__ W4, const float* __restrict__ B4,
    float* __restrict__ out)
{
    extern __shared__ float sm[];
    const int tid = threadIdx.x;
    const int w = tid >> 5;
    const int lane = tid & 31;
    const int g = lane >> 2;
    const int q = lane & 3;
    const int b = blockIdx.x;
    const int m = b & 63;
    const int j = b >> 6;
    const int nb = (m < 16) ? 10 : 9;
    const int base = g_offsets[m];
    const int cnt = g_offsets[m + 1] - base;
    if (j * 128 >= cnt) return;

    // ---- build fp16 fragment-ordered weights in SMEM ----
    {
        const float* Ws[3] = { W1 + m * 4096, W2 + m * 4096, W3 + m * 4096 };
        uint4* bf4 = (uint4*)(sm + OFF_BF);
        for (int l = 0; l < 3; l++) {
            const float* Wl = Ws[l];
            for (int jj = tid; jj < 512; jj += 128) {
                int ln = jj & 31, t = jj >> 5;   // t in [0,16)
                int kk = t >> 2, p = t & 3;
                int n0 = p * 16 + (ln >> 2);     // nn = 2p
                int n1 = n0 + 8;                 // nn = 2p+1
                int kb = kk * 16 + 2 * (ln & 3);
                float2 alo = *(const float2*)(Wl + n0 * 64 + kb);
                float2 ahi = *(const float2*)(Wl + n0 * 64 + kb + 8);
                float2 blo = *(const float2*)(Wl + n1 * 64 + kb);
                float2 bhi = *(const float2*)(Wl + n1 * 64 + kb + 8);
                bf4[l * 512 + jj] = make_uint4(packh2(alo.x, alo.y), packh2(ahi.x, ahi.y),
                                               packh2(blo.x, blo.y), packh2(bhi.x, bhi.y));
            }
        }
        // layer0 k8 frags (K padded to 8; k==6 carries bias via constant-1 input)
        uint32_t* b0f = (uint32_t*)(sm + OFF_B0F);
        for (int jj = tid; jj < 256; jj += 128) {
            int ln = jj & 31, nn = jj >> 5;
            int n = nn * 8 + (ln >> 2);
            int k0 = 2 * (ln & 3);                 // 0,2,4,6
            float v0 = (k0 < 6) ? W0[m * 384 + n * 6 + k0] : B0[m * 64 + n];
            float v1 = (k0 + 1 < 6) ? W0[m * 384 + n * 6 + k0 + 1] : 0.0f;
            b0f[jj] = packh2(v0, v1);
        }
        // head k16 frags: n = ln>>2 (rows 3..7 zero), same k layout as layers
        uint2* hf = (uint2*)(sm + OFF_HF);
        {
            int ln = tid & 31, kk = tid >> 5;
            if (kk < 4) {
                int n = ln >> 2;
                uint2 v = make_uint2(0u, 0u);
                if (n < 3) {
                    int kb = kk * 16 + 2 * (ln & 3);
                    const float* Wh = W4 + m * 192 + n * 64;
                    float2 wlo = *(const float2*)(Wh + kb);
                    float2 whi = *(const float2*)(Wh + kb + 8);
                    v = make_uint2(packh2(wlo.x, wlo.y), packh2(whi.x, whi.y));
                }
                hf[tid] = v;
            }
        }
        // interleaved G|H table: layer l in [0,4), element [nn*16 + 4q + c]
        //   c<2 -> G[nn*8+2q+c], c>=2 -> H[nn*8+2q+(c-2)]
        {
            const float* Gs[4] = { G0 + m * 64, G1 + m * 64, G2 + m * 64, G3 + m * 64 };
            const float* Hs[4] = { H0 + m * 64, H1 + m * 64, H2 + m * 64, H3 + m * 64 };
            for (int jj = tid; jj < 512; jj += 128) {
                int l = jj >> 7, r = jj & 127;
                int nn = r >> 4, qq = (r >> 2) & 3, c = r & 3;
                int f = nn * 8 + 2 * qq + (c & 1);
                sm[OFF_GHC + jj] = (c < 2) ? Gs[l][f] : Hs[l][f];
            }
        }
        // biases for layers 1..3 (float2-addressable, layout unchanged)
        {
            const float* Bs[3] = { B1 + m * 64, B2 + m * 64, B3 + m * 64 };
            for (int jj = tid; jj < 192; jj += 128)
                sm[OFF_BIAS + jj] = Bs[jj >> 6][jj & 63];
        }
        if (tid < 3) sm[OFF_B4 + tid] = B4[m * 3 + tid];
    }
    __syncthreads();

    uint32_t* stg = (uint32_t*)(sm + OFF_STAGE);
    const uint32_t* b0f = (const uint32_t*)(sm + OFF_B0F);
    const uint4* bf4 = (const uint4*)(sm + OFF_BF);
    const uint2* hf  = (const uint2*)(sm + OFF_HF) + lane;
    const int rbase = w * 32;
    const float b4_0 = sm[OFF_B4 + 0];
    const float b4_1 = sm[OFF_B4 + 1];
    const float b4_2 = sm[OFF_B4 + 2];

    // prefetch first pass's sample index
    int smp = g_perm[base + min(j * 128 + tid, cnt - 1)];

    for (int t0 = j * 128; t0 < cnt; t0 += nb * 128) {
        // stage this thread's sample row as 4 f16x2 words (6 feats + 1.0 + 0)
        {
            float2 x0 = *(const float2*)(x + smp * 6);
            float2 x1 = *(const float2*)(x + smp * 6 + 2);
            float2 x2 = *(const float2*)(x + smp * 6 + 4);
            stg[tid * 4 + 0] = packh2(x0.x, x0.y);
            stg[tid * 4 + 1] = packh2(x1.x, x1.y);
            stg[tid * 4 + 2] = packh2(x2.x, x2.y);
            stg[tid * 4 + 3] = 0x00003C00u;   // {lo=1.0h (bias), hi=0}
        }
        __syncwarp();

        // prefetch next pass's sample index (splits the perm->x latency chain)
        const int tn = t0 + nb * 128;
        int smp_n = 0;
        if (tn < cnt) smp_n = g_perm[base + min(tn + tid, cnt - 1)];

        float d0[8][4], d1[8][4];
        uint32_t ap0[8], ap1[8], bp0[8], bp1[8];

        // ---- layer 0: both m-tiles, k8 f16 (bias folded via constant-1) ----
        {
            uint32_t a00 = stg[(rbase + g) * 4 + q];
            uint32_t a01 = stg[(rbase + g + 8) * 4 + q];
            uint32_t a10 = stg[(rbase + 16 + g) * 4 + q];
            uint32_t a11 = stg[(rbase + 24 + g) * 4 + q];
#pragma unroll
            for (int nn = 0; nn < 8; nn++) {
                d0[nn][0] = d0[nn][1] = d0[nn][2] = d0[nn][3] = 0.f;
                d1[nn][0] = d1[nn][1] = d1[nn][2] = d1[nn][3] = 0.f;
                uint32_t bb = b0f[nn * 32 + lane];
                mma_f16_k8(d0[nn], a00, a01, bb);
                mma_f16_k8(d1[nn], a10, a11, bb);
            }
        }
        ln16x2_pack(d0, d1, sm + OFF_GHC, q, ap0, ap1, bp0, bp1);

        // ---- layers 1..3: k16 f16; bias as accumulator init; uint4 frags ----
#pragma unroll 1
        for (int l = 0; l < 3; l++) {
            const float* pB = sm + OFF_BIAS + l * 64;
#pragma unroll
            for (int nn = 0; nn < 8; nn++) {
                float2 bv = *(const float2*)(pB + nn * 8 + 2 * q);
                d0[nn][0] = bv.x; d0[nn][1] = bv.y; d0[nn][2] = bv.x; d0[nn][3] = bv.y;
                d1[nn][0] = bv.x; d1[nn][1] = bv.y; d1[nn][2] = bv.x; d1[nn][3] = bv.y;
            }
            const uint4* bl = bf4 + l * 512 + lane;
#pragma unroll
            for (int kk = 0; kk < 4; kk++) {
#pragma unroll
                for (int p = 0; p < 4; p++) {
                    uint4 bb = bl[(kk * 4 + p) * 32];
                    int n0 = 2 * p, n1 = 2 * p + 1;
                    mma_f16_k16(d0[n0], ap0[2 * kk], ap1[2 * kk],
                                ap0[2 * kk + 1], ap1[2 * kk + 1], bb.x, bb.y);
                    mma_f16_k16(d1[n0], bp0[2 * kk], bp1[2 * kk],
                                bp0[2 * kk + 1], bp1[2 * kk + 1], bb.x, bb.y);
                    mma_f16_k16(d0[n1], ap0[2 * kk], ap1[2 * kk],
                                ap0[2 * kk + 1], ap1[2 * kk + 1], bb.z, bb.w);
                    mma_f16_k16(d1[n1], bp0[2 * kk], bp1[2 * kk],
                                bp0[2 * kk + 1], bp1[2 * kk + 1], bb.z, bb.w);
                }
            }
            ln16x2_pack(d0, d1, sm + OFF_GHC + (l + 1) * 128, q, ap0, ap1, bp0, bp1);
        }

        // ---- head: 64 -> 3 via mma (N padded to 8) ----
        float e0[4] = {0.f, 0.f, 0.f, 0.f};
        float e1[4] = {0.f, 0.f, 0.f, 0.f};
#pragma unroll
        for (int kk = 0; kk < 4; kk++) {
            uint2 bb = hf[kk * 32];
            mma_f16_k16(e0, ap0[2 * kk], ap1[2 * kk], ap0[2 * kk + 1], ap1[2 * kk + 1],
                        bb.x, bb.y);
            mma_f16_k16(e1, bp0[2 * kk], bp1[2 * kk], bp0[2 * kk + 1], bp1[2 * kk + 1],
                        bb.x, bb.y);
        }
        // D frag: lane(g,q) holds (row g, col 2q), (row g, col 2q+1),
        //         (row g+8, col 2q), (row g+8, col 2q+1). Valid cols: 0,1,2.
        int s_r0 = __shfl_sync(0xffffffffu, smp, g);
        int s_r1 = __shfl_sync(0xffffffffu, smp, g + 8);
        int s_r2 = __shfl_sync(0xffffffffu, smp, 16 + g);
        int s_r3 = __shfl_sync(0xffffffffu, smp, 24 + g);
        int pr = t0 + rbase + g;
        if (q == 0) {
            if (pr < cnt)      { out[s_r0 * 3 + 0] = e0[0] + b4_0; out[s_r0 * 3 + 1] = e0[1] + b4_1; }
            if (pr + 8 < cnt)  { out[s_r1 * 3 + 0] = e0[2] + b4_0; out[s_r1 * 3 + 1] = e0[3] + b4_1; }
            if (pr + 16 < cnt) { out[s_r2 * 3 + 0] = e1[0] + b4_0; out[s_r2 * 3 + 1] = e1[1] + b4_1; }
            if (pr + 24 < cnt) { out[s_r3 * 3 + 0] = e1[2] + b4_0; out[s_r3 * 3 + 1] = e1[3] + b4_1; }
        } else if (q == 1) {
            if (pr < cnt)      out[s_r0 * 3 + 2] = e0[0] + b4_2;
            if (pr + 8 < cnt)  out[s_r1 * 3 + 2] = e0[2] + b4_2;
            if (pr + 16 < cnt) out[s_r2 * 3 + 2] = e1[0] + b4_2;
            if (pr + 24 < cnt) out[s_r3 * 3 + 2] = e1[2] + b4_2;
        }
        smp = smp_n;
    }
}

// ---------------- launch -----------------------------------------------------
extern "C" void kernel_launch(void* const* d_in, const int* in_sizes, int n_in,
                              void* d_out, int out_size) {
    const float* x  = (const float*)d_in[0];
    const int* idx  = (const int*)d_in[1];
    const float* W0 = (const float*)d_in[2];
    const float* B0 = (const float*)d_in[3];
    const float* G0 = (const float*)d_in[4];
    const float* H0 = (const float*)d_in[5];
    const float* W1 = (const float*)d_in[6];
    const float* B1 = (const float*)d_in[7];
    const float* G1 = (const float*)d_in[8];
    const float* H1 = (const float*)d_in[9];
    const float* W2 = (const float*)d_in[10];
    const float* B2 = (const float*)d_in[11];
    const float* G2 = (const float*)d_in[12];
    const float* H2 = (const float*)d_in[13];
    const float* W3 = (const float*)d_in[14];
    const float* B3 = (const float*)d_in[15];
    const float* G3 = (const float*)d_in[16];
    const float* H3 = (const float*)d_in[17];
    const float* W4 = (const float*)d_in[18];
    const float* B4 = (const float*)d_in[19];
    float* out = (float*)d_out;

    int N = in_sizes[1];
    if (N > MAXN) N = MAXN;

    cudaFuncSetAttribute(mlp_kernel, cudaFuncAttributeMaxDynamicSharedMemorySize,
                         SMEM_FLOATS * (int)sizeof(float));

    hist_kernel<<<512, 256>>>(idx, N);
    scan_kernel<<<1, 64>>>();
    scatter_kernel<<<512, 256>>>(idx, N);

    mlp_kernel<<<592, 128, SMEM_FLOATS * (int)sizeof(float)>>>(
        x, W0, B0, G0, H0, W1, B1, G1, H1, W2, B2, G2, H2, W3, B3, G3, H3, W4, B4, out);
}